// round 6
// baseline (speedup 1.0000x reference)
#include <cuda_runtime.h>

#define N_NODES 50000
#define N_EDGES 800000
#define IN_CH   100
#define HID     128
#define OUT_CH  47
#define OUT_P   48
#define ORIG    25000

#define CSR_NB  148
#define CSR_T   256
#define TILE_N  ((N_NODES + CSR_T - 1) / CSR_T)   // 196 tiles of 256

typedef unsigned long long U64;

static __device__ __forceinline__ U64 fma2(U64 a, U64 b, U64 c) {
    U64 d;
    asm("fma.rn.f32x2 %0, %1, %2, %3;" : "=l"(d) : "l"(a), "l"(b), "l"(c));
    return d;
}
static __device__ __forceinline__ float pairsum(U64 v) {
    float2 f = *reinterpret_cast<float2*>(&v);
    return f.x + f.y;
}

// ---- scratch ----
__device__ int    g_cnt [N_NODES];
__device__ int    g_off [N_NODES + 1];
__device__ int    g_wptr[N_NODES];          // write cursors for fill
__device__ int    g_bsum[TILE_N];
__device__ int    g_boff[TILE_N];
__device__ int    g_adj [N_EDGES];
__device__ float  g_agg1[(size_t)N_NODES * IN_CH];
__device__ float  g_h   [(size_t)N_NODES * HID];
__device__ float  g_g0  [(size_t)N_NODES * OUT_CH];
__device__ float  g_r0  [(size_t)ORIG * OUT_P];
__device__ float2 g_wp1l[50 * HID];
__device__ float2 g_wp1r[50 * HID];
__device__ float2 g_wp2l[64 * OUT_P];
__device__ float2 g_wp2r[64 * OUT_P];

// ---- grid barrier (generation-based; all CSR_NB blocks co-resident) ----
__device__ int g_bar_cnt = 0;
__device__ int g_bar_gen = 0;

static __device__ __forceinline__ void grid_barrier() {
    __syncthreads();
    __threadfence();
    if (threadIdx.x == 0) {
        int gen = atomicAdd(&g_bar_gen, 0);
        if (atomicAdd(&g_bar_cnt, 1) == CSR_NB - 1) {
            g_bar_cnt = 0;
            __threadfence();
            atomicAdd(&g_bar_gen, 1);
        } else {
            while (atomicAdd(&g_bar_gen, 0) == gen) __nanosleep(64);
        }
    }
    __syncthreads();
}

// ---- 1. fused CSR build: zero + prepack + count + scan + fill ----
__global__ void __launch_bounds__(CSR_T) k_csr(
        const int* __restrict__ src, const int* __restrict__ dst,
        const float* __restrict__ w1l, const float* __restrict__ w1r,
        const float* __restrict__ w2l, const float* __restrict__ w2r) {
    __shared__ int s[CSR_T];
    const int gid    = blockIdx.x * CSR_T + threadIdx.x;
    const int stride = CSR_NB * CSR_T;
    const int t      = threadIdx.x;

    // Phase A: zero counters + prepack weights
    for (int i = gid; i < N_NODES; i += stride) g_cnt[i] = 0;
    for (int i = gid; i < 50 * HID; i += stride) {
        int k2 = i / HID, c = i % HID;
        g_wp1l[i] = make_float2(w1l[(2 * k2) * HID + c], w1l[(2 * k2 + 1) * HID + c]);
        g_wp1r[i] = make_float2(w1r[(2 * k2) * HID + c], w1r[(2 * k2 + 1) * HID + c]);
    }
    for (int i = gid; i < 64 * OUT_P; i += stride) {
        int k2 = i / OUT_P, c = i % OUT_P;
        float l0 = 0.f, l1 = 0.f, r0 = 0.f, r1 = 0.f;
        if (c < OUT_CH) {
            l0 = w2l[(2 * k2) * OUT_CH + c]; l1 = w2l[(2 * k2 + 1) * OUT_CH + c];
            r0 = w2r[(2 * k2) * OUT_CH + c]; r1 = w2r[(2 * k2 + 1) * OUT_CH + c];
        }
        g_wp2l[i] = make_float2(l0, l1);
        g_wp2r[i] = make_float2(r0, r1);
    }
    grid_barrier();

    // Phase B: count in-degrees
    for (int i = gid; i < N_EDGES; i += stride)
        atomicAdd(&g_cnt[dst[i]], 1);
    grid_barrier();

    // Phase C: per-tile sums (tiles of 256 counts)
    for (int tile = blockIdx.x; tile < TILE_N; tile += CSR_NB) {
        int i = tile * CSR_T + t;
        int v = (i < N_NODES) ? g_cnt[i] : 0;
        s[t] = v;
        __syncthreads();
        for (int d = CSR_T / 2; d > 0; d >>= 1) {
            if (t < d) s[t] += s[t + d];
            __syncthreads();
        }
        if (t == 0) g_bsum[tile] = s[0];
        __syncthreads();
    }
    grid_barrier();

    // Phase D: block 0 scans the 196 tile sums
    if (blockIdx.x == 0) {
        int v = (t < TILE_N) ? g_bsum[t] : 0;
        s[t] = v;
        __syncthreads();
        for (int d = 1; d < CSR_T; d <<= 1) {
            int u = (t >= d) ? s[t - d] : 0;
            __syncthreads();
            s[t] += u;
            __syncthreads();
        }
        if (t < TILE_N) g_boff[t] = s[t] - v;
        if (t == TILE_N - 1) g_off[N_NODES] = s[t];
    }
    grid_barrier();

    // Phase E: per-tile local exclusive scan + tile offset -> g_off, g_wptr
    for (int tile = blockIdx.x; tile < TILE_N; tile += CSR_NB) {
        int i = tile * CSR_T + t;
        int v = (i < N_NODES) ? g_cnt[i] : 0;
        s[t] = v;
        __syncthreads();
        for (int d = 1; d < CSR_T; d <<= 1) {
            int u = (t >= d) ? s[t - d] : 0;
            __syncthreads();
            s[t] += u;
            __syncthreads();
        }
        if (i < N_NODES) {
            int o = g_boff[tile] + s[t] - v;
            g_off[i]  = o;
            g_wptr[i] = o;
        }
        __syncthreads();
    }
    grid_barrier();

    // Phase F: fill adjacency
    for (int i = gid; i < N_EDGES; i += stride) {
        int d = dst[i];
        int p = atomicAdd(&g_wptr[d], 1);
        g_adj[p] = src[i];
    }
}

// ---- 2. layer-1 mean aggregation (warp/node, fp32 gather) ----
__global__ void k_agg1(const float* __restrict__ x) {
    int w    = (blockIdx.x * blockDim.x + threadIdx.x) >> 5;
    int lane = threadIdx.x & 31;
    if (w >= N_NODES) return;
    int beg = g_off[w], end = g_off[w + 1];
    float4 acc = make_float4(0.f, 0.f, 0.f, 0.f);
    for (int e = beg; e < end; e++) {
        int s = g_adj[e];
        if (lane < IN_CH / 4) {
            float4 v = reinterpret_cast<const float4*>(x + (size_t)s * IN_CH)[lane];
            acc.x += v.x; acc.y += v.y; acc.z += v.z; acc.w += v.w;
        }
    }
    float inv = 1.f / fmaxf((float)(end - beg), 1.f);
    if (lane < IN_CH / 4) {
        acc.x *= inv; acc.y *= inv; acc.z *= inv; acc.w *= inv;
        reinterpret_cast<float4*>(g_agg1 + (size_t)w * IN_CH)[lane] = acc;
    }
}

// ---- 3. layer-1 GEMM (f32x2): h = agg1@w1l + x@w1r + b1  (32 rows, 128 thr) ----
__global__ void __launch_bounds__(128) k_gemm1(const float* __restrict__ x,
                                               const float* __restrict__ b1l) {
    __shared__ float sa[32 * IN_CH];
    __shared__ float sx[32 * IN_CH];
    int tid = threadIdx.x;
    int tx = tid & 31, ty = tid >> 5;
    int row0 = blockIdx.x * 32;
    for (int i = tid; i < 32 * 25; i += 128) {
        int r = i / 25, c4 = i % 25;
        int node = row0 + r;
        float4 va = make_float4(0.f, 0.f, 0.f, 0.f), vx = va;
        if (node < N_NODES) {
            va = reinterpret_cast<const float4*>(g_agg1 + (size_t)node * IN_CH)[c4];
            vx = reinterpret_cast<const float4*>(x + (size_t)node * IN_CH)[c4];
        }
        reinterpret_cast<float4*>(sa + r * IN_CH)[c4] = va;
        reinterpret_cast<float4*>(sx + r * IN_CH)[c4] = vx;
    }
    __syncthreads();

    U64 acc[8][4];
#pragma unroll
    for (int r = 0; r < 8; r++)
#pragma unroll
        for (int c = 0; c < 4; c++) acc[r][c] = 0ull;

#pragma unroll 1
    for (int kk = 0; kk < 25; kk++) {
        const ulonglong2* wl0 = reinterpret_cast<const ulonglong2*>(g_wp1l + (2 * kk) * HID + 4 * tx);
        const ulonglong2* wl1 = reinterpret_cast<const ulonglong2*>(g_wp1l + (2 * kk + 1) * HID + 4 * tx);
        const ulonglong2* wr0 = reinterpret_cast<const ulonglong2*>(g_wp1r + (2 * kk) * HID + 4 * tx);
        const ulonglong2* wr1 = reinterpret_cast<const ulonglong2*>(g_wp1r + (2 * kk + 1) * HID + 4 * tx);
        ulonglong2 l0 = wl0[0], l0b = wl0[1];
        ulonglong2 l1 = wl1[0], l1b = wl1[1];
        ulonglong2 r0 = wr0[0], r0b = wr0[1];
        ulonglong2 r1 = wr1[0], r1b = wr1[1];
        U64 wl2[2][4] = {{l0.x, l0.y, l0b.x, l0b.y}, {l1.x, l1.y, l1b.x, l1b.y}};
        U64 wr2[2][4] = {{r0.x, r0.y, r0b.x, r0b.y}, {r1.x, r1.y, r1b.x, r1b.y}};
#pragma unroll
        for (int r = 0; r < 8; r++) {
            int row = ty * 8 + r;
            ulonglong2 av = *reinterpret_cast<const ulonglong2*>(sa + row * IN_CH + 4 * kk);
            ulonglong2 xv = *reinterpret_cast<const ulonglong2*>(sx + row * IN_CH + 4 * kk);
#pragma unroll
            for (int c = 0; c < 4; c++) {
                acc[r][c] = fma2(av.x, wl2[0][c], acc[r][c]);
                acc[r][c] = fma2(av.y, wl2[1][c], acc[r][c]);
                acc[r][c] = fma2(xv.x, wr2[0][c], acc[r][c]);
                acc[r][c] = fma2(xv.y, wr2[1][c], acc[r][c]);
            }
        }
    }
    float4 bias = reinterpret_cast<const float4*>(b1l)[tx];
#pragma unroll
    for (int r = 0; r < 8; r++) {
        int node = row0 + ty * 8 + r;
        if (node < N_NODES) {
            float4 o;
            o.x = pairsum(acc[r][0]) + bias.x;
            o.y = pairsum(acc[r][1]) + bias.y;
            o.z = pairsum(acc[r][2]) + bias.z;
            o.w = pairsum(acc[r][3]) + bias.w;
            reinterpret_cast<float4*>(g_h + (size_t)node * HID)[tx] = o;
        }
    }
}

// ---- 4. layer-2 GEMMs: g0 = h@w2l (all rows); r0 = h@w2r + b2 (rows < ORIG) ----
__global__ void __launch_bounds__(128) k_gemm2(const float* __restrict__ b2) {
    __shared__ float sh[32 * HID];
    int tid = threadIdx.x;
    int tx = tid & 63, ty = tid >> 6;
    int row0 = blockIdx.x * 32;
    for (int i = tid; i < 32 * 32; i += 128) {
        int r = i >> 5, c4 = i & 31;
        int node = row0 + r;
        float4 v = make_float4(0.f, 0.f, 0.f, 0.f);
        if (node < N_NODES) v = reinterpret_cast<const float4*>(g_h + (size_t)node * HID)[c4];
        reinterpret_cast<float4*>(sh + r * HID)[c4] = v;
    }
    __syncthreads();
    if (tx >= OUT_P) return;
    bool do_r = (row0 < ORIG);
    int col = tx;
    U64 accg[16], accr[16];
#pragma unroll
    for (int r = 0; r < 16; r++) { accg[r] = 0ull; accr[r] = 0ull; }

#pragma unroll 1
    for (int kk = 0; kk < 32; kk++) {
        float2 wg0f = g_wp2l[(2 * kk) * OUT_P + col];
        float2 wg1f = g_wp2l[(2 * kk + 1) * OUT_P + col];
        U64 wg0 = *reinterpret_cast<U64*>(&wg0f);
        U64 wg1 = *reinterpret_cast<U64*>(&wg1f);
        U64 wr0 = 0ull, wr1 = 0ull;
        if (do_r) {
            float2 a = g_wp2r[(2 * kk) * OUT_P + col];
            float2 b = g_wp2r[(2 * kk + 1) * OUT_P + col];
            wr0 = *reinterpret_cast<U64*>(&a);
            wr1 = *reinterpret_cast<U64*>(&b);
        }
#pragma unroll
        for (int r = 0; r < 16; r++) {
            int row = ty * 16 + r;
            ulonglong2 hv = *reinterpret_cast<const ulonglong2*>(sh + row * HID + 4 * kk);
            accg[r] = fma2(hv.x, wg0, accg[r]);
            accg[r] = fma2(hv.y, wg1, accg[r]);
            if (do_r) {
                accr[r] = fma2(hv.x, wr0, accr[r]);
                accr[r] = fma2(hv.y, wr1, accr[r]);
            }
        }
    }
    float bv = (col < OUT_CH) ? b2[col] : 0.f;
#pragma unroll
    for (int r = 0; r < 16; r++) {
        int node = row0 + ty * 16 + r;
        if (node < N_NODES && col < OUT_CH)
            g_g0[(size_t)node * OUT_CH + col] = pairsum(accg[r]);
        if (node < ORIG)
            g_r0[(size_t)node * OUT_P + col] = pairsum(accr[r]) + bv;
    }
}

// ---- 5. final: out = log_softmax(mean_nbr(g0) + r0)  for i < ORIG ----
__global__ void k_final(float* __restrict__ out) {
    int w    = (blockIdx.x * blockDim.x + threadIdx.x) >> 5;
    int lane = threadIdx.x & 31;
    if (w >= ORIG) return;
    int beg = g_off[w], end = g_off[w + 1];
    float a0 = 0.f, a1 = 0.f;
    for (int e = beg; e < end; e++) {
        int s = g_adj[e];
        const float* row = g_g0 + (size_t)s * OUT_CH;
        a0 += __ldg(row + lane);
        if (lane < OUT_CH - 32) a1 += __ldg(row + 32 + lane);
    }
    float inv = 1.f / fmaxf((float)(end - beg), 1.f);
    const float* r0row = g_r0 + (size_t)w * OUT_P;
    a0 = a0 * inv + r0row[lane];
    if (lane < OUT_CH - 32) a1 = a1 * inv + r0row[32 + lane];

    float m = a0;
    if (lane < OUT_CH - 32) m = fmaxf(m, a1);
#pragma unroll
    for (int o = 16; o > 0; o >>= 1) m = fmaxf(m, __shfl_xor_sync(0xffffffffu, m, o));
    float e0 = expf(a0 - m);
    float e1 = (lane < OUT_CH - 32) ? expf(a1 - m) : 0.f;
    float ss = e0 + e1;
#pragma unroll
    for (int o = 16; o > 0; o >>= 1) ss += __shfl_xor_sync(0xffffffffu, ss, o);
    float ls = m + logf(ss);
    out[(size_t)w * OUT_CH + lane] = a0 - ls;
    if (lane < OUT_CH - 32) out[(size_t)w * OUT_CH + 32 + lane] = a1 - ls;
}

extern "C" void kernel_launch(void* const* d_in, const int* in_sizes, int n_in,
                              void* d_out, int out_size) {
    const float* x   = (const float*)d_in[0];
    const int*   ei  = (const int*)  d_in[1];
    const int*   src = ei;
    const int*   dst = ei + N_EDGES;
    const float* w1l = (const float*)d_in[3];
    const float* b1l = (const float*)d_in[4];
    const float* w1r = (const float*)d_in[5];
    const float* w2l = (const float*)d_in[6];
    const float* b2l = (const float*)d_in[7];
    const float* w2r = (const float*)d_in[8];
    float* out = (float*)d_out;

    k_csr  <<<CSR_NB, CSR_T>>>(src, dst, w1l, w1r, w2l, w2r);
    k_agg1 <<<(N_NODES * 32 + 255) / 256, 256>>>(x);
    k_gemm1<<<(N_NODES + 31) / 32, 128>>>(x, b1l);
    k_gemm2<<<(N_NODES + 31) / 32, 128>>>(b2l);
    k_final<<<(ORIG * 32 + 255) / 256, 256>>>(out);
}

// round 7
// speedup vs baseline: 1.5847x; 1.5847x over previous
#include <cuda_runtime.h>
#include <cstdint>

#define N_NODES 50000
#define N_EDGES 800000
#define IN_CH   100
#define HID     128
#define OUT_CH  47
#define OUT_P   48
#define ORIG    25000

#define SCAN_BS   256
#define SCAN_NB   ((N_NODES + SCAN_BS - 1) / SCAN_BS)   // 196

#define K1   208          // padded K for layer1 (104 agg + 104 x)
#define K1C  (K1 / 8)     // 26 chunks
#define K2C  (HID / 8)    // 16 chunks
#define N2   96           // layer2 N: 48 g0-cols + 48 r0-cols
#define SB1  132          // sB stride gemm1
#define SB2  100          // sB stride gemm2

// ---- scratch ----
__device__ int    g_cnt [N_NODES];
__device__ int    g_fill[N_NODES];
__device__ int    g_off [N_NODES + 1];
__device__ int    g_bsum[SCAN_NB];
__device__ int    g_boff[SCAN_NB];
__device__ int    g_adj [N_EDGES];
__device__ float  g_agg1[(size_t)N_NODES * IN_CH];
__device__ float  g_h   [(size_t)N_NODES * HID];
__device__ float  g_g0  [(size_t)N_NODES * OUT_P];   // stride 48 (col 47 pad)
__device__ float  g_r0  [(size_t)ORIG * OUT_P];
__device__ float  g_B1  [K1 * HID];                  // tf32 [208][128]
__device__ float  g_B2  [HID * N2];                  // tf32 [128][96]

static __device__ __forceinline__ float to_tf32(float f) {
    uint32_t o;
    asm("cvt.rna.tf32.f32 %0, %1;" : "=r"(o) : "f"(f));
    return __uint_as_float(o);
}
static __device__ __forceinline__ void mma_tf32(float* c, uint32_t a0, uint32_t a1,
                                                uint32_t a2, uint32_t a3,
                                                uint32_t b0, uint32_t b1) {
    asm("mma.sync.aligned.m16n8k8.row.col.f32.tf32.tf32.f32 "
        "{%0,%1,%2,%3},{%4,%5,%6,%7},{%8,%9},{%0,%1,%2,%3};"
        : "+f"(c[0]), "+f"(c[1]), "+f"(c[2]), "+f"(c[3])
        : "r"(a0), "r"(a1), "r"(a2), "r"(a3), "r"(b0), "r"(b1));
}

// ---- 1. zero counters + prepack B1/B2 (tf32) ----
__global__ void k_pre(const float* __restrict__ w1l, const float* __restrict__ w1r,
                      const float* __restrict__ w2l, const float* __restrict__ w2r) {
    int i = blockIdx.x * blockDim.x + threadIdx.x;
    if (i < N_NODES) { g_cnt[i] = 0; g_fill[i] = 0; }
    if (i < K1 * HID) {
        int k = i / HID, c = i % HID;
        float v = 0.f;
        if (k < IN_CH)                         v = w1l[k * HID + c];
        else if (k >= 104 && k < 104 + IN_CH)  v = w1r[(k - 104) * HID + c];
        g_B1[i] = to_tf32(v);
    }
    if (i < HID * N2) {
        int k = i / N2, c = i % N2;
        float v = 0.f;
        if (c < OUT_CH)                        v = w2l[k * OUT_CH + c];
        else if (c >= 48 && c < 48 + OUT_CH)   v = w2r[k * OUT_CH + (c - 48)];
        g_B2[i] = to_tf32(v);
    }
}

// ---- 2. count in-degree ----
__global__ void k_count(const int* __restrict__ dst) {
    int i = blockIdx.x * blockDim.x + threadIdx.x;
    if (i < N_EDGES) atomicAdd(&g_cnt[dst[i]], 1);
}

// ---- 3a. per-block sums ----
__global__ void k_blocksum() {
    __shared__ int s[SCAN_BS];
    int i = blockIdx.x * SCAN_BS + threadIdx.x;
    int v = (i < N_NODES) ? g_cnt[i] : 0;
    s[threadIdx.x] = v;
    __syncthreads();
    for (int d = SCAN_BS / 2; d > 0; d >>= 1) {
        if (threadIdx.x < d) s[threadIdx.x] += s[threadIdx.x + d];
        __syncthreads();
    }
    if (threadIdx.x == 0) g_bsum[blockIdx.x] = s[0];
}

// ---- 3b. scan block sums ----
__global__ void k_scanb() {
    __shared__ int s[SCAN_BS];
    int t = threadIdx.x;
    int v = (t < SCAN_NB) ? g_bsum[t] : 0;
    s[t] = v;
    __syncthreads();
    for (int d = 1; d < SCAN_BS; d <<= 1) {
        int u = (t >= d) ? s[t - d] : 0;
        __syncthreads();
        s[t] += u;
        __syncthreads();
    }
    if (t < SCAN_NB) g_boff[t] = s[t] - v;
    if (t == SCAN_NB - 1) g_off[N_NODES] = s[t];
}

// ---- 3c. local scan + offset ----
__global__ void k_offsets() {
    __shared__ int s[SCAN_BS];
    int t = threadIdx.x;
    int i = blockIdx.x * SCAN_BS + t;
    int v = (i < N_NODES) ? g_cnt[i] : 0;
    s[t] = v;
    __syncthreads();
    for (int d = 1; d < SCAN_BS; d <<= 1) {
        int u = (t >= d) ? s[t - d] : 0;
        __syncthreads();
        s[t] += u;
        __syncthreads();
    }
    if (i < N_NODES) g_off[i] = g_boff[blockIdx.x] + s[t] - v;
}

// ---- 4. fill CSR ----
__global__ void k_fill(const int* __restrict__ src, const int* __restrict__ dst) {
    int i = blockIdx.x * blockDim.x + threadIdx.x;
    if (i < N_EDGES) {
        int d = dst[i];
        int p = atomicAdd(&g_fill[d], 1);
        g_adj[g_off[d] + p] = src[i];
    }
}

// ---- 5. layer-1 mean aggregation (warp/node, fp32) ----
__global__ void k_agg1(const float* __restrict__ x) {
    int w    = (blockIdx.x * blockDim.x + threadIdx.x) >> 5;
    int lane = threadIdx.x & 31;
    if (w >= N_NODES) return;
    int beg = g_off[w], end = g_off[w + 1];
    float4 acc = make_float4(0.f, 0.f, 0.f, 0.f);
    for (int e = beg; e < end; e++) {
        int s = g_adj[e];
        if (lane < IN_CH / 4) {
            float4 v = reinterpret_cast<const float4*>(x + (size_t)s * IN_CH)[lane];
            acc.x += v.x; acc.y += v.y; acc.z += v.z; acc.w += v.w;
        }
    }
    float inv = 1.f / fmaxf((float)(end - beg), 1.f);
    if (lane < IN_CH / 4) {
        acc.x *= inv; acc.y *= inv; acc.z *= inv; acc.w *= inv;
        reinterpret_cast<float4*>(g_agg1 + (size_t)w * IN_CH)[lane] = acc;
    }
}

// ---- 6. layer-1 GEMM via tf32 mma: h[128r x 128c] per block ----
// A = [agg1 | x] zero-padded to K=208.  8 warps: wm 0..3 (32 rows), wn 0..1 (64 cols).
__global__ void __launch_bounds__(256) k_gemm1(const float* __restrict__ x,
                                               const float* __restrict__ b1l) {
    __shared__ float sA[128 * 8];
    __shared__ float sB[8 * SB1];
    const int tid  = threadIdx.x;
    const int lane = tid & 31;
    const int warp = tid >> 5;
    const int wm   = warp & 3;
    const int wn   = warp >> 2;
    const int gr   = lane >> 2;     // 0..7
    const int kc   = lane & 3;      // 0..3
    const int row0 = blockIdx.x * 128;

    // staging indices
    const int srow = tid >> 1;           // 0..127
    const int skq  = (tid & 1) * 4;      // 0 or 4
    const int bk   = tid >> 5;           // 0..7
    const int bn0  = (tid & 31) * 4;     // 0..124

    float acc[2][8][4];
#pragma unroll
    for (int mt = 0; mt < 2; mt++)
#pragma unroll
        for (int nt = 0; nt < 8; nt++)
#pragma unroll
            for (int j = 0; j < 4; j++) acc[mt][nt][j] = 0.f;

    // load chunk 0 into regs
    float4 aReg, bReg;
    {
        int node = row0 + srow;
        int ks = skq;                    // chunk 0
        float4 v = make_float4(0.f, 0.f, 0.f, 0.f);
        if (node < N_NODES && ks < IN_CH)
            v = *reinterpret_cast<const float4*>(g_agg1 + (size_t)node * IN_CH + ks);
        aReg = v;
        bReg = *reinterpret_cast<const float4*>(g_B1 + bk * HID + bn0);
    }

#pragma unroll 1
    for (int c = 0; c < K1C; c++) {
        __syncthreads();
        // store staged chunk
        float4 av;
        av.x = to_tf32(aReg.x); av.y = to_tf32(aReg.y);
        av.z = to_tf32(aReg.z); av.w = to_tf32(aReg.w);
        *reinterpret_cast<float4*>(sA + srow * 8 + skq) = av;
        *reinterpret_cast<float4*>(sB + bk * SB1 + bn0) = bReg;
        __syncthreads();

        // prefetch next chunk
        if (c + 1 < K1C) {
            int k0 = (c + 1) * 8;
            int node = row0 + srow;
            int ks = k0 + skq;
            float4 v = make_float4(0.f, 0.f, 0.f, 0.f);
            if (node < N_NODES) {
                if (ks < IN_CH)
                    v = *reinterpret_cast<const float4*>(g_agg1 + (size_t)node * IN_CH + ks);
                else if (ks >= 104 && ks < 204)
                    v = *reinterpret_cast<const float4*>(x + (size_t)node * IN_CH + (ks - 104));
            }
            aReg = v;
            bReg = *reinterpret_cast<const float4*>(g_B1 + (k0 + bk) * HID + bn0);
        }

        // mma on current chunk
        uint32_t afr[2][4];
#pragma unroll
        for (int mt = 0; mt < 2; mt++) {
            int ar = wm * 32 + mt * 16 + gr;
            afr[mt][0] = __float_as_uint(sA[ar * 8 + kc]);
            afr[mt][1] = __float_as_uint(sA[(ar + 8) * 8 + kc]);
            afr[mt][2] = __float_as_uint(sA[ar * 8 + kc + 4]);
            afr[mt][3] = __float_as_uint(sA[(ar + 8) * 8 + kc + 4]);
        }
#pragma unroll
        for (int nt = 0; nt < 8; nt++) {
            int bc = wn * 64 + nt * 8 + gr;
            uint32_t b0 = __float_as_uint(sB[kc * SB1 + bc]);
            uint32_t b1 = __float_as_uint(sB[(kc + 4) * SB1 + bc]);
            mma_tf32(acc[0][nt], afr[0][0], afr[0][1], afr[0][2], afr[0][3], b0, b1);
            mma_tf32(acc[1][nt], afr[1][0], afr[1][1], afr[1][2], afr[1][3], b0, b1);
        }
    }

    // epilogue: + bias, store h
#pragma unroll
    for (int mt = 0; mt < 2; mt++) {
#pragma unroll
        for (int nt = 0; nt < 8; nt++) {
            int col = wn * 64 + nt * 8 + 2 * kc;
            float2 bv = *reinterpret_cast<const float2*>(b1l + col);
            int r1 = row0 + wm * 32 + mt * 16 + gr;
            if (r1 < N_NODES) {
                float2 o = make_float2(acc[mt][nt][0] + bv.x, acc[mt][nt][1] + bv.y);
                *reinterpret_cast<float2*>(g_h + (size_t)r1 * HID + col) = o;
            }
            int r2 = r1 + 8;
            if (r2 < N_NODES) {
                float2 o = make_float2(acc[mt][nt][2] + bv.x, acc[mt][nt][3] + bv.y);
                *reinterpret_cast<float2*>(g_h + (size_t)r2 * HID + col) = o;
            }
        }
    }
}

// ---- 7. layer-2 GEMM via tf32 mma: [g0 | r0] = h @ [w2l | w2r] ----
// N=96: wn=0 -> g0 cols (stride-48 padded), wn=1 -> r0 cols (+bias, rows < ORIG)
__global__ void __launch_bounds__(256) k_gemm2(const float* __restrict__ b2) {
    __shared__ float sA[128 * 8];
    __shared__ float sB[8 * SB2];
    const int tid  = threadIdx.x;
    const int lane = tid & 31;
    const int warp = tid >> 5;
    const int wm   = warp & 3;
    const int wn   = warp >> 2;
    const int gr   = lane >> 2;
    const int kc   = lane & 3;
    const int row0 = blockIdx.x * 128;

    const int srow = tid >> 1;
    const int skq  = (tid & 1) * 4;
    const bool doB = (tid < 192);
    const int bk   = tid / 24;
    const int bn0  = (tid % 24) * 4;

    const bool active = (wn == 0) || (row0 < ORIG);

    float acc[2][6][4];
#pragma unroll
    for (int mt = 0; mt < 2; mt++)
#pragma unroll
        for (int nt = 0; nt < 6; nt++)
#pragma unroll
            for (int j = 0; j < 4; j++) acc[mt][nt][j] = 0.f;

    float4 aReg, bReg;
    {
        int node = row0 + srow;
        float4 v = make_float4(0.f, 0.f, 0.f, 0.f);
        if (node < N_NODES)
            v = *reinterpret_cast<const float4*>(g_h + (size_t)node * HID + skq);
        aReg = v;
        if (doB) bReg = *reinterpret_cast<const float4*>(g_B2 + bk * N2 + bn0);
    }

#pragma unroll 1
    for (int c = 0; c < K2C; c++) {
        __syncthreads();
        float4 av;
        av.x = to_tf32(aReg.x); av.y = to_tf32(aReg.y);
        av.z = to_tf32(aReg.z); av.w = to_tf32(aReg.w);
        *reinterpret_cast<float4*>(sA + srow * 8 + skq) = av;
        if (doB) *reinterpret_cast<float4*>(sB + bk * SB2 + bn0) = bReg;
        __syncthreads();

        if (c + 1 < K2C) {
            int k0 = (c + 1) * 8;
            int node = row0 + srow;
            float4 v = make_float4(0.f, 0.f, 0.f, 0.f);
            if (node < N_NODES)
                v = *reinterpret_cast<const float4*>(g_h + (size_t)node * HID + k0 + skq);
            aReg = v;
            if (doB) bReg = *reinterpret_cast<const float4*>(g_B2 + (k0 + bk) * N2 + bn0);
        }

        if (active) {
            uint32_t afr[2][4];
#pragma unroll
            for (int mt = 0; mt < 2; mt++) {
                int ar = wm * 32 + mt * 16 + gr;
                afr[mt][0] = __float_as_uint(sA[ar * 8 + kc]);
                afr[mt][1] = __float_as_uint(sA[(ar + 8) * 8 + kc]);
                afr[mt][2] = __float_as_uint(sA[ar * 8 + kc + 4]);
                afr[mt][3] = __float_as_uint(sA[(ar + 8) * 8 + kc + 4]);
            }
#pragma unroll
            for (int nt = 0; nt < 6; nt++) {
                int bc = wn * 48 + nt * 8 + gr;
                uint32_t b0 = __float_as_uint(sB[kc * SB2 + bc]);
                uint32_t b1 = __float_as_uint(sB[(kc + 4) * SB2 + bc]);
                mma_tf32(acc[0][nt], afr[0][0], afr[0][1], afr[0][2], afr[0][3], b0, b1);
                mma_tf32(acc[1][nt], afr[1][0], afr[1][1], afr[1][2], afr[1][3], b0, b1);
            }
        }
    }

    if (!active) return;

#pragma unroll
    for (int mt = 0; mt < 2; mt++) {
#pragma unroll
        for (int nt = 0; nt < 6; nt++) {
            int colL = nt * 8 + 2 * kc;          // 0..46 (even)
            int r1 = row0 + wm * 32 + mt * 16 + gr;
            int r2 = r1 + 8;
            if (wn == 0) {
                if (r1 < N_NODES)
                    *reinterpret_cast<float2*>(g_g0 + (size_t)r1 * OUT_P + colL) =
                        make_float2(acc[mt][nt][0], acc[mt][nt][1]);
                if (r2 < N_NODES)
                    *reinterpret_cast<float2*>(g_g0 + (size_t)r2 * OUT_P + colL) =
                        make_float2(acc[mt][nt][2], acc[mt][nt][3]);
            } else {
                float bx = b2[colL];
                float by = (colL + 1 < OUT_CH) ? b2[colL + 1] : 0.f;
                if (r1 < ORIG)
                    *reinterpret_cast<float2*>(g_r0 + (size_t)r1 * OUT_P + colL) =
                        make_float2(acc[mt][nt][0] + bx, acc[mt][nt][1] + by);
                if (r2 < ORIG)
                    *reinterpret_cast<float2*>(g_r0 + (size_t)r2 * OUT_P + colL) =
                        make_float2(acc[mt][nt][2] + bx, acc[mt][nt][3] + by);
            }
        }
    }
}

// ---- 8. final: out = log_softmax(mean_nbr(g0) + r0)  for i < ORIG ----
__global__ void k_final(float* __restrict__ out) {
    int w    = (blockIdx.x * blockDim.x + threadIdx.x) >> 5;
    int lane = threadIdx.x & 31;
    if (w >= ORIG) return;
    int beg = g_off[w], end = g_off[w + 1];
    float a0 = 0.f, a1 = 0.f;
    for (int e = beg; e < end; e++) {
        int s = g_adj[e];
        const float* row = g_g0 + (size_t)s * OUT_P;
        a0 += __ldg(row + lane);
        if (lane < OUT_CH - 32) a1 += __ldg(row + 32 + lane);
    }
    float inv = 1.f / fmaxf((float)(end - beg), 1.f);
    const float* r0row = g_r0 + (size_t)w * OUT_P;
    a0 = a0 * inv + r0row[lane];
    if (lane < OUT_CH - 32) a1 = a1 * inv + r0row[32 + lane];

    float m = a0;
    if (lane < OUT_CH - 32) m = fmaxf(m, a1);
#pragma unroll
    for (int o = 16; o > 0; o >>= 1) m = fmaxf(m, __shfl_xor_sync(0xffffffffu, m, o));
    float e0 = expf(a0 - m);
    float e1 = (lane < OUT_CH - 32) ? expf(a1 - m) : 0.f;
    float ss = e0 + e1;
#pragma unroll
    for (int o = 16; o > 0; o >>= 1) ss += __shfl_xor_sync(0xffffffffu, ss, o);
    float ls = m + logf(ss);
    out[(size_t)w * OUT_CH + lane] = a0 - ls;
    if (lane < OUT_CH - 32) out[(size_t)w * OUT_CH + 32 + lane] = a1 - ls;
}

extern "C" void kernel_launch(void* const* d_in, const int* in_sizes, int n_in,
                              void* d_out, int out_size) {
    const float* x   = (const float*)d_in[0];
    const int*   ei  = (const int*)  d_in[1];
    const int*   src = ei;
    const int*   dst = ei + N_EDGES;
    const float* w1l = (const float*)d_in[3];
    const float* b1l = (const float*)d_in[4];
    const float* w1r = (const float*)d_in[5];
    const float* w2l = (const float*)d_in[6];
    const float* b2l = (const float*)d_in[7];
    const float* w2r = (const float*)d_in[8];
    float* out = (float*)d_out;

    const int GB = (N_NODES + 127) / 128;   // 391

    k_pre     <<<SCAN_NB, SCAN_BS>>>(w1l, w1r, w2l, w2r);
    k_count   <<<(N_EDGES + 255) / 256, 256>>>(dst);
    k_blocksum<<<SCAN_NB, SCAN_BS>>>();
    k_scanb   <<<1, SCAN_BS>>>();
    k_offsets <<<SCAN_NB, SCAN_BS>>>();
    k_fill    <<<(N_EDGES + 255) / 256, 256>>>(src, dst);
    k_agg1    <<<(N_NODES * 32 + 255) / 256, 256>>>(x);
    k_gemm1   <<<GB, 256>>>(x, b1l);
    k_gemm2   <<<GB, 256>>>(b2l);
    k_final   <<<(ORIG * 32 + 255) / 256, 256>>>(out);
}